// round 2
// baseline (speedup 1.0000x reference)
#include <cuda_runtime.h>
#include <stdint.h>

// Problem constants (from reference): HIDDEN=128, NUM_RADIAL=6.
#define HIDDEN 128
#define NRAD   6

__global__ void zero_out_kernel(float4* __restrict__ out, int n4) {
    int idx = blockIdx.x * blockDim.x + threadIdx.x;
    int stride = gridDim.x * blockDim.x;
    for (int k = idx; k < n4; k += stride)
        out[k] = make_float4(0.f, 0.f, 0.f, 0.f);
}

// One warp per edge. lane owns channels [4*lane, 4*lane+4).
// coef[h] = sum_r rbf[e][r] * W[h][r];  msg = coef * x[e];  red.add into out[i[e]].
__global__ void __launch_bounds__(256)
fused_rbf_scatter_kernel(const float* __restrict__ x,
                         const float* __restrict__ rbf,
                         const float* __restrict__ W,   // [HIDDEN, NRAD] row-major
                         const int* __restrict__ idx,   // int32 edge indices (JAX demotes int64)
                         float* __restrict__ out,
                         int E)
{
    const int lane  = threadIdx.x & 31;
    const int warp  = (blockIdx.x * blockDim.x + threadIdx.x) >> 5;
    const int nwarp = (gridDim.x * blockDim.x) >> 5;

    // Load this lane's 4 rows of W (24 floats) into registers once.
    const int hbase = lane * 4;
    float w[4][NRAD];
#pragma unroll
    for (int j = 0; j < 4; ++j)
#pragma unroll
        for (int r = 0; r < NRAD; ++r)
            w[j][r] = W[(hbase + j) * NRAD + r];

    const float4* __restrict__ x4 = reinterpret_cast<const float4*>(x);

    for (int e = warp; e < E; e += nwarp) {
        // node index (uniform per warp; all lanes load same 4B, L1-cached)
        int node = idx[e];

        // rbf row: lanes 0..5 each grab one value, broadcast via shfl
        float rv = (lane < NRAD) ? rbf[(size_t)e * NRAD + lane] : 0.0f;

        float c0 = 0.f, c1 = 0.f, c2 = 0.f, c3 = 0.f;
#pragma unroll
        for (int r = 0; r < NRAD; ++r) {
            float rr = __shfl_sync(0xffffffffu, rv, r);
            c0 = fmaf(rr, w[0][r], c0);
            c1 = fmaf(rr, w[1][r], c1);
            c2 = fmaf(rr, w[2][r], c2);
            c3 = fmaf(rr, w[3][r], c3);
        }

        // coalesced 512B row read of x
        float4 xv = x4[(size_t)e * (HIDDEN / 4) + lane];

        float m0 = c0 * xv.x;
        float m1 = c1 * xv.y;
        float m2 = c2 * xv.z;
        float m3 = c3 * xv.w;

        float* dst = out + (size_t)node * HIDDEN + hbase;  // 16B aligned
        asm volatile("red.global.add.v4.f32 [%0], {%1, %2, %3, %4};"
                     :: "l"(dst), "f"(m0), "f"(m1), "f"(m2), "f"(m3)
                     : "memory");
    }
}

extern "C" void kernel_launch(void* const* d_in, const int* in_sizes, int n_in,
                              void* d_out, int out_size)
{
    const float* x   = (const float*)d_in[0];   // [E, 128]
    const float* rbf = (const float*)d_in[1];   // [E, 6]
    const float* W   = (const float*)d_in[2];   // [128, 6]
    const int*   idx = (const int*)d_in[3];     // [E] int32
    float*       out = (float*)d_out;           // [num_nodes, 128]

    const int E = in_sizes[0] / HIDDEN;

    // Zero output (poisoned to 0xAA by harness)
    {
        int n4 = out_size / 4;
        int threads = 256;
        int blocks = (n4 + threads - 1) / threads;
        if (blocks > 8192) blocks = 8192;
        zero_out_kernel<<<blocks, threads>>>((float4*)out, n4);
    }

    // Fused compute + scatter-add: one warp per edge, grid-stride
    {
        int threads = 256;                 // 8 warps / block
        int blocks  = 148 * 24;            // plenty of waves, amortize W loads
        int warps_needed = (E + 7) / 8;
        if (blocks > warps_needed) blocks = warps_needed;
        fused_rbf_scatter_kernel<<<blocks, threads>>>(x, rbf, W, idx, out, E);
    }
}

// round 3
// speedup vs baseline: 1.3735x; 1.3735x over previous
#include <cuda_runtime.h>
#include <stdint.h>

#define HIDDEN 128
#define NRAD   6

__global__ void zero_out_kernel(float4* __restrict__ out, int n4) {
    int idx = blockIdx.x * blockDim.x + threadIdx.x;
    int stride = gridDim.x * blockDim.x;
    for (int k = idx; k < n4; k += stride)
        out[k] = make_float4(0.f, 0.f, 0.f, 0.f);
}

// One warp per 2 consecutive edges. lane owns channels [4*lane, 4*lane+4).
__global__ void __launch_bounds__(256)
fused_rbf_scatter_kernel(const float* __restrict__ x,
                         const float* __restrict__ rbf,
                         const float* __restrict__ W,   // [HIDDEN, NRAD] row-major
                         const int* __restrict__ idx,   // int32 edge indices
                         float* __restrict__ out,
                         int E)
{
    const int lane  = threadIdx.x & 31;
    const int warp  = (blockIdx.x * blockDim.x + threadIdx.x) >> 5;
    const int nwarp = (gridDim.x * blockDim.x) >> 5;

    // This lane's 4 rows of W (24 floats) in registers.
    const int hbase = lane * 4;
    float w[4][NRAD];
#pragma unroll
    for (int j = 0; j < 4; ++j)
#pragma unroll
        for (int r = 0; r < NRAD; ++r)
            w[j][r] = W[(hbase + j) * NRAD + r];

    const float4* __restrict__ x4   = reinterpret_cast<const float4*>(x);
    const float2* __restrict__ rbf2 = reinterpret_cast<const float2*>(rbf); // row e = float2 [3e..3e+2]

    for (int e0 = warp * 2; e0 < E; e0 += nwarp * 2) {
        const int e1 = e0 + 1;
        const bool has1 = (e1 < E);

        // ---- issue ALL loads up front (streaming / evict-first) ----
        int node0 = __ldcs(idx + e0);
        int node1 = has1 ? __ldcs(idx + e1) : 0;

        float2 a0 = __ldcs(rbf2 + (size_t)e0 * 3 + 0);
        float2 a1 = __ldcs(rbf2 + (size_t)e0 * 3 + 1);
        float2 a2 = __ldcs(rbf2 + (size_t)e0 * 3 + 2);

        float2 b0, b1, b2;
        if (has1) {
            b0 = __ldcs(rbf2 + (size_t)e1 * 3 + 0);
            b1 = __ldcs(rbf2 + (size_t)e1 * 3 + 1);
            b2 = __ldcs(rbf2 + (size_t)e1 * 3 + 2);
        } else {
            b0 = b1 = b2 = make_float2(0.f, 0.f);
        }

        float4 xv0 = __ldcs(x4 + (size_t)e0 * (HIDDEN / 4) + lane);
        float4 xv1 = has1 ? __ldcs(x4 + (size_t)e1 * (HIDDEN / 4) + lane)
                          : make_float4(0.f, 0.f, 0.f, 0.f);

        // ---- compute coefficients (independent FMA trees) ----
        float c[4], d[4];
#pragma unroll
        for (int j = 0; j < 4; ++j) {
            c[j] = fmaf(a0.x, w[j][0],
                   fmaf(a0.y, w[j][1],
                   fmaf(a1.x, w[j][2],
                   fmaf(a1.y, w[j][3],
                   fmaf(a2.x, w[j][4], a2.y * w[j][5])))));
            d[j] = fmaf(b0.x, w[j][0],
                   fmaf(b0.y, w[j][1],
                   fmaf(b1.x, w[j][2],
                   fmaf(b1.y, w[j][3],
                   fmaf(b2.x, w[j][4], b2.y * w[j][5])))));
        }

        float m0 = c[0] * xv0.x, m1 = c[1] * xv0.y, m2 = c[2] * xv0.z, m3 = c[3] * xv0.w;
        float n0 = d[0] * xv1.x, n1 = d[1] * xv1.y, n2 = d[2] * xv1.z, n3 = d[3] * xv1.w;

        float* dst0 = out + (size_t)node0 * HIDDEN + hbase;
        asm volatile("red.global.add.v4.f32 [%0], {%1, %2, %3, %4};"
                     :: "l"(dst0), "f"(m0), "f"(m1), "f"(m2), "f"(m3) : "memory");
        if (has1) {
            float* dst1 = out + (size_t)node1 * HIDDEN + hbase;
            asm volatile("red.global.add.v4.f32 [%0], {%1, %2, %3, %4};"
                         :: "l"(dst1), "f"(n0), "f"(n1), "f"(n2), "f"(n3) : "memory");
        }
    }
}

extern "C" void kernel_launch(void* const* d_in, const int* in_sizes, int n_in,
                              void* d_out, int out_size)
{
    const float* x   = (const float*)d_in[0];   // [E, 128]
    const float* rbf = (const float*)d_in[1];   // [E, 6]
    const float* W   = (const float*)d_in[2];   // [128, 6]
    const int*   idx = (const int*)d_in[3];     // [E] int32
    float*       out = (float*)d_out;           // [num_nodes, 128]

    const int E = in_sizes[0] / HIDDEN;

    // Zero output (poisoned to 0xAA by harness)
    {
        int n4 = out_size / 4;
        int threads = 256;
        int blocks = (n4 + threads - 1) / threads;
        if (blocks > 8192) blocks = 8192;
        zero_out_kernel<<<blocks, threads>>>((float4*)out, n4);
    }

    // Fused compute + scatter-add: one warp per 2 edges, grid-stride
    {
        int threads = 256;                  // 8 warps / block
        int blocks  = 148 * 24;             // 3552 blocks
        int warps_needed = (E + 15) / 16;   // 2 edges per warp per iter
        if (blocks > warps_needed) blocks = warps_needed;
        fused_rbf_scatter_kernel<<<blocks, threads>>>(x, rbf, W, idx, out, E);
    }
}

// round 4
// speedup vs baseline: 1.4886x; 1.0838x over previous
#include <cuda_runtime.h>
#include <stdint.h>

#define HIDDEN 128
#define NRAD   6

__global__ void zero_out_kernel(float4* __restrict__ out, int n4) {
    int idx = blockIdx.x * blockDim.x + threadIdx.x;
    int stride = gridDim.x * blockDim.x;
    for (int k = idx; k < n4; k += stride)
        out[k] = make_float4(0.f, 0.f, 0.f, 0.f);
}

__device__ __forceinline__ uint32_t smem_u32(const void* p) {
    uint32_t a;
    asm("{ .reg .u64 t; cvta.to.shared.u64 t, %1; cvt.u32.u64 %0, t; }"
        : "=r"(a) : "l"(p));
    return a;
}

// One warp per 2 consecutive edges. lane owns channels [4*lane, 4*lane+4).
// W kept in SMEM (reloaded per iter) to free registers -> 6 CTAs/SM.
__global__ void __launch_bounds__(256, 6)
fused_rbf_scatter_kernel(const float* __restrict__ x,
                         const float* __restrict__ rbf,
                         const float* __restrict__ W,   // [HIDDEN, NRAD] row-major
                         const int* __restrict__ idx,   // int32 edge indices
                         float* __restrict__ out,
                         int E)
{
    __shared__ float4 sW[NRAD][32];   // sW[r][lane] = W[4l+0..3][r]

    const int tid  = threadIdx.x;
    const int lane = tid & 31;

    for (int t = tid; t < NRAD * 32; t += blockDim.x) {
        int l = t / NRAD;
        int r = t - l * NRAD;
        sW[r][l] = make_float4(W[(4 * l + 0) * NRAD + r],
                               W[(4 * l + 1) * NRAD + r],
                               W[(4 * l + 2) * NRAD + r],
                               W[(4 * l + 3) * NRAD + r]);
    }
    __syncthreads();

    const uint32_t sW_base = smem_u32(&sW[0][0]) + lane * 16u;

    const int warp  = (blockIdx.x * blockDim.x + tid) >> 5;
    const int nwarp = (gridDim.x * blockDim.x) >> 5;

    const float4* __restrict__ x4   = reinterpret_cast<const float4*>(x);
    const float4* __restrict__ rbf4 = reinterpret_cast<const float4*>(rbf);

    for (int p = warp; 2 * p < E; p += nwarp) {
        const int  e0   = 2 * p;
        const bool has1 = (e0 + 1 < E);

        // ---- all loads up front (streaming) ----
        int node0 = __ldcs(idx + e0);
        int node1 = has1 ? __ldcs(idx + e0 + 1) : 0;

        // two rbf rows = 48 contiguous bytes, 16B-aligned (e0 even)
        float4 f0, f1, f2;
        if (has1) {
            f0 = __ldcs(rbf4 + 3 * (size_t)p);
            f1 = __ldcs(rbf4 + 3 * (size_t)p + 1);
            f2 = __ldcs(rbf4 + 3 * (size_t)p + 2);
        } else {
            const float2* r2 = reinterpret_cast<const float2*>(rbf) + 3 * (size_t)e0;
            float2 g0 = __ldcs(r2), g1 = __ldcs(r2 + 1), g2 = __ldcs(r2 + 2);
            f0 = make_float4(g0.x, g0.y, g1.x, g1.y);
            f1 = make_float4(g2.x, g2.y, 0.f, 0.f);
            f2 = make_float4(0.f, 0.f, 0.f, 0.f);
        }

        float4 xv0 = __ldcs(x4 + (size_t)e0 * (HIDDEN / 4) + lane);
        float4 xv1 = has1 ? __ldcs(x4 + ((size_t)e0 + 1) * (HIDDEN / 4) + lane)
                          : make_float4(0.f, 0.f, 0.f, 0.f);

        const float a[NRAD] = {f0.x, f0.y, f0.z, f0.w, f1.x, f1.y};
        const float b[NRAD] = {f1.z, f1.w, f2.x, f2.y, f2.z, f2.w};

        float c0 = 0.f, c1 = 0.f, c2 = 0.f, c3 = 0.f;
        float d0 = 0.f, d1 = 0.f, d2 = 0.f, d3 = 0.f;

#pragma unroll
        for (int r = 0; r < NRAD; ++r) {
            float w0, w1, w2, w3;
            // forced per-iteration LDS (prevents ptxas hoisting W into 24 regs)
            asm volatile("ld.shared.v4.f32 {%0,%1,%2,%3}, [%4];"
                         : "=f"(w0), "=f"(w1), "=f"(w2), "=f"(w3)
                         : "r"(sW_base + (uint32_t)(r * 32 * 16)));
            c0 = fmaf(a[r], w0, c0);  d0 = fmaf(b[r], w0, d0);
            c1 = fmaf(a[r], w1, c1);  d1 = fmaf(b[r], w1, d1);
            c2 = fmaf(a[r], w2, c2);  d2 = fmaf(b[r], w2, d2);
            c3 = fmaf(a[r], w3, c3);  d3 = fmaf(b[r], w3, d3);
        }

        float m0 = c0 * xv0.x, m1 = c1 * xv0.y, m2 = c2 * xv0.z, m3 = c3 * xv0.w;
        float n0 = d0 * xv1.x, n1 = d1 * xv1.y, n2 = d2 * xv1.z, n3 = d3 * xv1.w;

        float* dst0 = out + (size_t)node0 * HIDDEN + lane * 4;
        asm volatile("red.global.add.v4.f32 [%0], {%1, %2, %3, %4};"
                     :: "l"(dst0), "f"(m0), "f"(m1), "f"(m2), "f"(m3) : "memory");
        if (has1) {
            float* dst1 = out + (size_t)node1 * HIDDEN + lane * 4;
            asm volatile("red.global.add.v4.f32 [%0], {%1, %2, %3, %4};"
                         :: "l"(dst1), "f"(n0), "f"(n1), "f"(n2), "f"(n3) : "memory");
        }
    }
}

extern "C" void kernel_launch(void* const* d_in, const int* in_sizes, int n_in,
                              void* d_out, int out_size)
{
    const float* x   = (const float*)d_in[0];   // [E, 128]
    const float* rbf = (const float*)d_in[1];   // [E, 6]
    const float* W   = (const float*)d_in[2];   // [128, 6]
    const int*   idx = (const int*)d_in[3];     // [E] int32
    float*       out = (float*)d_out;           // [num_nodes, 128]

    const int E = in_sizes[0] / HIDDEN;

    // Zero output (poisoned to 0xAA by harness)
    {
        int n4 = out_size / 4;
        int threads = 256;
        int blocks = (n4 + threads - 1) / threads;
        if (blocks > 8192) blocks = 8192;
        zero_out_kernel<<<blocks, threads>>>((float4*)out, n4);
    }

    // Fused compute + scatter-add
    {
        int threads = 256;                  // 8 warps / block
        int blocks  = 148 * 24;             // 3552 blocks
        int warps_needed = (E + 15) / 16;
        if (blocks > warps_needed) blocks = warps_needed;
        fused_rbf_scatter_kernel<<<blocks, threads>>>(x, rbf, W, idx, out, E);
    }
}

// round 5
// speedup vs baseline: 1.5612x; 1.0488x over previous
#include <cuda_runtime.h>
#include <stdint.h>

#define HIDDEN 128
#define NRAD   6

__global__ void zero_out_kernel(float4* __restrict__ out, int n4) {
    int idx = blockIdx.x * blockDim.x + threadIdx.x;
    int stride = gridDim.x * blockDim.x;
    for (int k = idx; k < n4; k += stride)
        out[k] = make_float4(0.f, 0.f, 0.f, 0.f);
}

// 1 edge per warp-iteration, contiguous per-warp edge chunks.
// W register-resident (24 regs). lane owns channels [4*lane, 4*lane+4).
// 1-deep software prefetch on the x row to get MLP=2 per warp.
__global__ void __launch_bounds__(256, 5)
fused_rbf_scatter_kernel(const float* __restrict__ x,
                         const float* __restrict__ rbf,
                         const float* __restrict__ W,   // [HIDDEN, NRAD] row-major
                         const int* __restrict__ idx,   // int32 edge indices
                         float* __restrict__ out,
                         int E)
{
    const int lane  = threadIdx.x & 31;
    const int wid   = (blockIdx.x * blockDim.x + threadIdx.x) >> 5;
    const int nwarp = (gridDim.x * blockDim.x) >> 5;

    // This lane's 4 rows of W (24 floats) in registers, loaded once.
    const int hbase = lane * 4;
    float w00,w01,w02,w03,w04,w05;
    float w10,w11,w12,w13,w14,w15;
    float w20,w21,w22,w23,w24,w25;
    float w30,w31,w32,w33,w34,w35;
    {
        const float* p = W + hbase * NRAD;
        w00=p[0];  w01=p[1];  w02=p[2];  w03=p[3];  w04=p[4];  w05=p[5];
        w10=p[6];  w11=p[7];  w12=p[8];  w13=p[9];  w14=p[10]; w15=p[11];
        w20=p[12]; w21=p[13]; w22=p[14]; w23=p[15]; w24=p[16]; w25=p[17];
        w30=p[18]; w31=p[19]; w32=p[20]; w33=p[21]; w34=p[22]; w35=p[23];
    }

    const float4* __restrict__ x4   = reinterpret_cast<const float4*>(x);
    const float2* __restrict__ rbf2 = reinterpret_cast<const float2*>(rbf);

    // Contiguous chunk per warp: rbf/idx lines L1-hit across iterations,
    // x reads and RED writes are sequential streams.
    const int chunk = (E + nwarp - 1) / nwarp;
    int e   = wid * chunk;
    int end = e + chunk;
    if (end > E) end = E;
    if (e >= end) return;

    float4 cur = __ldcs(x4 + (size_t)e * (HIDDEN / 4) + lane);

    for (; e < end; ++e) {
        // prefetch next x row (MLP=2)
        float4 nxt = cur;
        if (e + 1 < end)
            nxt = __ldcs(x4 + (size_t)(e + 1) * (HIDDEN / 4) + lane);

        int node = idx[e];                       // L1-cached, uniform per warp
        float2 f0 = rbf2[3 * (size_t)e];
        float2 f1 = rbf2[3 * (size_t)e + 1];
        float2 f2 = rbf2[3 * (size_t)e + 2];

        float c0 = fmaf(f0.x, w00, fmaf(f0.y, w01, fmaf(f1.x, w02,
                   fmaf(f1.y, w03, fmaf(f2.x, w04, f2.y * w05)))));
        float c1 = fmaf(f0.x, w10, fmaf(f0.y, w11, fmaf(f1.x, w12,
                   fmaf(f1.y, w13, fmaf(f2.x, w14, f2.y * w15)))));
        float c2 = fmaf(f0.x, w20, fmaf(f0.y, w21, fmaf(f1.x, w22,
                   fmaf(f1.y, w23, fmaf(f2.x, w24, f2.y * w25)))));
        float c3 = fmaf(f0.x, w30, fmaf(f0.y, w31, fmaf(f1.x, w32,
                   fmaf(f1.y, w33, fmaf(f2.x, w34, f2.y * w35)))));

        float m0 = c0 * cur.x;
        float m1 = c1 * cur.y;
        float m2 = c2 * cur.z;
        float m3 = c3 * cur.w;

        float* dst = out + (size_t)node * HIDDEN + hbase;   // 16B aligned
        asm volatile("red.global.add.v4.f32 [%0], {%1, %2, %3, %4};"
                     :: "l"(dst), "f"(m0), "f"(m1), "f"(m2), "f"(m3) : "memory");

        cur = nxt;
    }
}

extern "C" void kernel_launch(void* const* d_in, const int* in_sizes, int n_in,
                              void* d_out, int out_size)
{
    const float* x   = (const float*)d_in[0];   // [E, 128]
    const float* rbf = (const float*)d_in[1];   // [E, 6]
    const float* W   = (const float*)d_in[2];   // [128, 6]
    const int*   idx = (const int*)d_in[3];     // [E] int32
    float*       out = (float*)d_out;           // [num_nodes, 128]

    const int E = in_sizes[0] / HIDDEN;

    // Zero output (poisoned to 0xAA by harness)
    {
        int n4 = out_size / 4;
        int threads = 256;
        int blocks = (n4 + threads - 1) / threads;
        if (blocks > 8192) blocks = 8192;
        zero_out_kernel<<<blocks, threads>>>((float4*)out, n4);
    }

    // Fused compute + scatter-add: 5 CTAs/SM * 148 SMs, 8 warps each.
    {
        int threads = 256;
        int blocks  = 148 * 5;              // 740 blocks -> 5920 warps
        int warps_needed = E;               // at most 1 warp per edge
        int max_blocks = (warps_needed + 7) / 8;
        if (blocks > max_blocks) blocks = max_blocks;
        fused_rbf_scatter_kernel<<<blocks, threads>>>(x, rbf, W, idx, out, E);
    }
}

// round 6
// speedup vs baseline: 1.6002x; 1.0250x over previous
#include <cuda_runtime.h>
#include <stdint.h>

#define HIDDEN 128
#define NRAD   6

__global__ void zero_out_kernel(float4* __restrict__ out, int n4) {
    int idx = blockIdx.x * blockDim.x + threadIdx.x;
    int stride = gridDim.x * blockDim.x;
    for (int k = idx; k < n4; k += stride)
        out[k] = make_float4(0.f, 0.f, 0.f, 0.f);
}

// One warp processes a contiguous chunk of edge PAIRS, 2 edges per iteration,
// with both next-pair x rows prefetched (2 LDG.128 in flight per warp).
// lane owns channels [4*lane, 4*lane+4). W register-resident.
__global__ void __launch_bounds__(128, 8)
fused_rbf_scatter_kernel(const float* __restrict__ x,
                         const float* __restrict__ rbf,
                         const float* __restrict__ W,   // [HIDDEN, NRAD] row-major
                         const int* __restrict__ idx,   // int32 edge indices
                         float* __restrict__ out,
                         int E)
{
    const int lane  = threadIdx.x & 31;
    const int wid   = (blockIdx.x * blockDim.x + threadIdx.x) >> 5;
    const int nwarp = (gridDim.x * blockDim.x) >> 5;

    // This lane's 4 rows of W (24 floats) in registers, loaded once.
    const int hbase = lane * 4;
    float w00,w01,w02,w03,w04,w05;
    float w10,w11,w12,w13,w14,w15;
    float w20,w21,w22,w23,w24,w25;
    float w30,w31,w32,w33,w34,w35;
    {
        const float* p = W + hbase * NRAD;
        w00=p[0];  w01=p[1];  w02=p[2];  w03=p[3];  w04=p[4];  w05=p[5];
        w10=p[6];  w11=p[7];  w12=p[8];  w13=p[9];  w14=p[10]; w15=p[11];
        w20=p[12]; w21=p[13]; w22=p[14]; w23=p[15]; w24=p[16]; w25=p[17];
        w30=p[18]; w31=p[19]; w32=p[20]; w33=p[21]; w34=p[22]; w35=p[23];
    }

    const float4* __restrict__ x4   = reinterpret_cast<const float4*>(x);
    const float4* __restrict__ rbf4 = reinterpret_cast<const float4*>(rbf);
    const int2*   __restrict__ idx2 = reinterpret_cast<const int2*>(idx);

    const int pairsFull = E >> 1;           // full pairs only (tail handled below)
    const int chunk = (pairsFull + nwarp - 1) / nwarp;
    int p    = wid * chunk;
    int pend = p + chunk;
    if (pend > pairsFull) pend = pairsFull;

    if (p < pend) {
        float4 cur0 = __ldcs(x4 + (size_t)(2 * p)     * (HIDDEN / 4) + lane);
        float4 cur1 = __ldcs(x4 + (size_t)(2 * p + 1) * (HIDDEN / 4) + lane);

        for (; p < pend; ++p) {
            // ---- prefetch next pair's x rows (2 LDG.128 in flight) ----
            float4 nxt0 = cur0, nxt1 = cur1;
            if (p + 1 < pend) {
                nxt0 = __ldcs(x4 + (size_t)(2 * p + 2) * (HIDDEN / 4) + lane);
                nxt1 = __ldcs(x4 + (size_t)(2 * p + 3) * (HIDDEN / 4) + lane);
            }

            int2   nodes = __ldcs(idx2 + p);                 // both edge indices, 8B
            float4 f0 = __ldcs(rbf4 + 3 * (size_t)p);        // rbf rows for the pair
            float4 f1 = __ldcs(rbf4 + 3 * (size_t)p + 1);    // (48B, 16B-aligned)
            float4 f2 = __ldcs(rbf4 + 3 * (size_t)p + 2);

            // edge0 coefficients: rbf = {f0.x,f0.y,f0.z,f0.w,f1.x,f1.y}
            float c0 = fmaf(f0.x, w00, fmaf(f0.y, w01, fmaf(f0.z, w02,
                       fmaf(f0.w, w03, fmaf(f1.x, w04, f1.y * w05)))));
            float c1 = fmaf(f0.x, w10, fmaf(f0.y, w11, fmaf(f0.z, w12,
                       fmaf(f0.w, w13, fmaf(f1.x, w14, f1.y * w15)))));
            float c2 = fmaf(f0.x, w20, fmaf(f0.y, w21, fmaf(f0.z, w22,
                       fmaf(f0.w, w23, fmaf(f1.x, w24, f1.y * w25)))));
            float c3 = fmaf(f0.x, w30, fmaf(f0.y, w31, fmaf(f0.z, w32,
                       fmaf(f0.w, w33, fmaf(f1.x, w34, f1.y * w35)))));

            // edge1 coefficients: rbf = {f1.z,f1.w,f2.x,f2.y,f2.z,f2.w}
            float d0 = fmaf(f1.z, w00, fmaf(f1.w, w01, fmaf(f2.x, w02,
                       fmaf(f2.y, w03, fmaf(f2.z, w04, f2.w * w05)))));
            float d1 = fmaf(f1.z, w10, fmaf(f1.w, w11, fmaf(f2.x, w12,
                       fmaf(f2.y, w13, fmaf(f2.z, w14, f2.w * w15)))));
            float d2 = fmaf(f1.z, w20, fmaf(f1.w, w21, fmaf(f2.x, w22,
                       fmaf(f2.y, w23, fmaf(f2.z, w24, f2.w * w25)))));
            float d3 = fmaf(f1.z, w30, fmaf(f1.w, w31, fmaf(f2.x, w32,
                       fmaf(f2.y, w33, fmaf(f2.z, w34, f2.w * w35)))));

            float m0 = c0 * cur0.x, m1 = c1 * cur0.y, m2 = c2 * cur0.z, m3 = c3 * cur0.w;
            float n0 = d0 * cur1.x, n1 = d1 * cur1.y, n2 = d2 * cur1.z, n3 = d3 * cur1.w;

            float* dst0 = out + (size_t)nodes.x * HIDDEN + hbase;
            asm volatile("red.global.add.v4.f32 [%0], {%1, %2, %3, %4};"
                         :: "l"(dst0), "f"(m0), "f"(m1), "f"(m2), "f"(m3) : "memory");
            float* dst1 = out + (size_t)nodes.y * HIDDEN + hbase;
            asm volatile("red.global.add.v4.f32 [%0], {%1, %2, %3, %4};"
                         :: "l"(dst1), "f"(n0), "f"(n1), "f"(n2), "f"(n3) : "memory");

            cur0 = nxt0;
            cur1 = nxt1;
        }
    }

    // Odd tail edge (E odd): warp 0 handles it.
    if ((E & 1) && wid == 0) {
        const int e = E - 1;
        int node = idx[e];
        const float2* r2 = reinterpret_cast<const float2*>(rbf) + 3 * (size_t)e;
        float2 g0 = r2[0], g1 = r2[1], g2 = r2[2];
        float4 xv = x4[(size_t)e * (HIDDEN / 4) + lane];

        float c0 = fmaf(g0.x, w00, fmaf(g0.y, w01, fmaf(g1.x, w02,
                   fmaf(g1.y, w03, fmaf(g2.x, w04, g2.y * w05)))));
        float c1 = fmaf(g0.x, w10, fmaf(g0.y, w11, fmaf(g1.x, w12,
                   fmaf(g1.y, w13, fmaf(g2.x, w14, g2.y * w15)))));
        float c2 = fmaf(g0.x, w20, fmaf(g0.y, w21, fmaf(g1.x, w22,
                   fmaf(g1.y, w23, fmaf(g2.x, w24, g2.y * w25)))));
        float c3 = fmaf(g0.x, w30, fmaf(g0.y, w31, fmaf(g1.x, w32,
                   fmaf(g1.y, w33, fmaf(g2.x, w34, g2.y * w35)))));

        float* dst = out + (size_t)node * HIDDEN + hbase;
        asm volatile("red.global.add.v4.f32 [%0], {%1, %2, %3, %4};"
                     :: "l"(dst), "f"(c0 * xv.x), "f"(c1 * xv.y),
                        "f"(c2 * xv.z), "f"(c3 * xv.w) : "memory");
    }
}

extern "C" void kernel_launch(void* const* d_in, const int* in_sizes, int n_in,
                              void* d_out, int out_size)
{
    const float* x   = (const float*)d_in[0];   // [E, 128]
    const float* rbf = (const float*)d_in[1];   // [E, 6]
    const float* W   = (const float*)d_in[2];   // [128, 6]
    const int*   idx = (const int*)d_in[3];     // [E] int32
    float*       out = (float*)d_out;           // [num_nodes, 128]

    const int E = in_sizes[0] / HIDDEN;

    // Zero output (poisoned to 0xAA by harness)
    {
        int n4 = out_size / 4;
        int threads = 256;
        int blocks = (n4 + threads - 1) / threads;
        if (blocks > 8192) blocks = 8192;
        zero_out_kernel<<<blocks, threads>>>((float4*)out, n4);
    }

    // Fused compute + scatter-add: 8 CTAs/SM * 148 SMs, 4 warps each.
    {
        int threads = 128;
        int blocks  = 148 * 8;              // 1184 blocks -> 4736 warps
        int pairs = E >> 1;
        int max_blocks = (pairs + 3) / 4;
        if (max_blocks < 1) max_blocks = 1;
        if (blocks > max_blocks) blocks = max_blocks;
        fused_rbf_scatter_kernel<<<blocks, threads>>>(x, rbf, W, idx, out, E);
    }
}